// round 8
// baseline (speedup 1.0000x reference)
#include <cuda_runtime.h>

#define TPB     256
#define NBINS   64
#define SBINS   56           // max bin = ceil(31.5*sqrt(3)) = 55
#define CPS     7            // CTAs per SM
#define GRID    (148 * CPS)  // 1036 blocks, single wave
#define NPTS    4096
#define NUNITS  2048         // row-pairs (u, n-1-u): each exactly 4095 pairs

// Scratch (allocation-free __device__ globals). g_hist/g_done/g_unit are zero
// at entry of every launch; the finalizing block resets them (replay-safe).
// g_pts is rewritten by the repack kernel at the start of every launch.
__device__ float4   g_pts[NPTS];
__device__ int      g_hist[NBINS];
__device__ unsigned g_done = 0;
__device__ unsigned g_unit = 0;

// Repack x[4096,3] (packed) -> g_pts[4096] (float4, w=0). 1024 threads.
__global__ void repack_kernel(const float* __restrict__ x) {
    const int g = blockIdx.x * blockDim.x + threadIdx.x;   // 0..1023
    const float4* x4 = (const float4*)x;
    const float4 a = __ldg(&x4[3 * g + 0]);
    const float4 b = __ldg(&x4[3 * g + 1]);
    const float4 c = __ldg(&x4[3 * g + 2]);
    g_pts[4 * g + 0] = make_float4(a.x, a.y, a.z, 0.0f);
    g_pts[4 * g + 1] = make_float4(a.w, b.x, b.y, 0.0f);
    g_pts[4 * g + 2] = make_float4(b.z, b.w, c.x, 0.0f);
    g_pts[4 * g + 3] = make_float4(c.y, c.z, c.w, 0.0f);
}

__global__ __launch_bounds__(TPB, CPS)
void ecc_kernel(float* __restrict__ out, int n) {
    // u16 hist [56][256]: column tid -> byte 2*tid + 512*bin.
    // bank = tid/2 for ANY bin pattern -> conflict-free RMW.
    __shared__ unsigned short sh[SBINS * TPB];
    __shared__ int      s_u;
    __shared__ float    s_wsum;
    __shared__ unsigned s_last;

    const int tid = threadIdx.x;
    unsigned* h32 = (unsigned*)sh;
    #pragma unroll
    for (int k = tid; k < SBINS * TPB / 2; k += TPB) h32[k] = 0u;

    unsigned short* myh = sh + tid;

    // Dynamic work queue over uniform units (near-perfect balance)
    for (;;) {
        if (tid == 0) s_u = (int)atomicAdd(&g_unit, 1u);
        __syncthreads();                       // also covers zero-init (1st iter)
        const int u = s_u;
        if (u >= NUNITS) break;

        int rows[2];
        rows[0] = u;
        rows[1] = n - 1 - u;
        #pragma unroll
        for (int rr = 0; rr < 2; rr++) {
            const int i = rows[rr];
            const float4 pi = __ldg(&g_pts[i]);
            #pragma unroll 4
            for (int j = i + 1 + tid; j < n; j += TPB) {
                const float4 pj = __ldg(&g_pts[j]);   // ONE LDG.128 per pair
                const float dx = pi.x - pj.x;
                const float dy = pi.y - pj.y;
                const float dz = pi.z - pj.z;
                const float s  = dx * dx + dy * dy + dz * dz;  // FMA ok (tol 1e-3)
                float r;
                // ceil(31.5*sqrt(s)) == ceil(sqrt(992.25*s)); approx ok at tol
                asm("sqrt.approx.f32 %0, %1;" : "=f"(r) : "f"(992.25f * s));
                int b = __float2int_ru(r);     // s==0 -> 0 -> bin 0 (= ref)
                b = min(b, SBINS - 1);
                myh[b * TPB] += 1;             // u16 RMW, conflict-free
            }
        }
        __syncthreads();                       // protect s_u for next fetch
    }
    __syncthreads();                           // RMWs visible to reducers

    // Block-reduce [56][128 words] -> g_hist: 4 threads/bin, rotated banks
    if (tid < SBINS * 4) {
        const int b = tid >> 2;
        const int q = tid & 3;
        const unsigned* hb = h32 + b * 128;
        unsigned sum = 0;
        #pragma unroll
        for (int k = 0; k < 32; k++) {
            const unsigned v = hb[q * 32 + ((k + tid) & 31)];
            sum += (v & 0xFFFFu) + (v >> 16);
        }
        sum += __shfl_xor_sync(0xffffffffu, sum, 1);
        sum += __shfl_xor_sync(0xffffffffu, sum, 2);
        if (q == 0 && sum) atomicAdd(&g_hist[b], (int)sum);
    }
    __syncthreads();

    // Last-done block: parallel 64-bin read + 2-warp shfl scan
    if (tid == 0) {
        __threadfence();
        s_last = (atomicAdd(&g_done, 1u) == (unsigned)GRID - 1u);
    }
    __syncthreads();
    if (s_last) {
        float v = 0.0f;
        if (tid < NBINS) {
            const int h = atomicAdd(&g_hist[tid], 0);   // 64 parallel reads
            v = -(float)h;
            if (tid == 0) v += (float)n;                // +n vertices at filt 0
            #pragma unroll
            for (int d = 1; d < 32; d <<= 1) {          // inclusive warp scan
                const float t = __shfl_up_sync(0xffffffffu, v, d);
                if ((tid & 31) >= d) v += t;
            }
            if (tid == 31) s_wsum = v;                  // warp0 total
        }
        __syncthreads();
        if (tid < NBINS) {
            if (tid >= 32) v += s_wsum;
            out[tid] = v;
            g_hist[tid] = 0;                            // reset for next replay
        }
        if (tid == 0) { g_unit = 0; g_done = 0; }
    }
}

extern "C" void kernel_launch(void* const* d_in, const int* in_sizes, int n_in,
                              void* d_out, int out_size) {
    const float* x = (const float*)d_in[0];
    float* out = (float*)d_out;
    const int n = in_sizes[0] / 3;   // 4096
    repack_kernel<<<4, 256>>>(x);
    ecc_kernel<<<GRID, TPB>>>(out, n);
}

// round 9
// speedup vs baseline: 1.2280x; 1.2280x over previous
#include <cuda_runtime.h>

#define TPB     256
#define NBINS   64
#define SBINS   56           // max bin = ceil(31.5*sqrt(3)) = 55
#define CPS     7            // CTAs per SM
#define GRID    (148 * CPS)  // 1036 blocks, single wave
#define NUNITS  2048         // units: adjacent row pairs (2k, 2k+1)

// Scratch (allocation-free __device__ globals). Zero at entry of every
// launch; the finalizing block resets them (graph-replay safe).
__device__ int      g_hist[NBINS];
__device__ unsigned g_done = 0;
__device__ unsigned g_unit = 0;

__device__ __forceinline__ int pair_bin(float dx, float dy, float dz) {
    const float s = dx * dx + dy * dy + dz * dz;   // FMA ok (tol 1e-3)
    float r;
    // ceil(31.5*sqrt(s)) == ceil(sqrt(992.25*s)); approx err ~1e-7 rel
    asm("sqrt.approx.f32 %0, %1;" : "=f"(r) : "f"(992.25f * s));
    return min(__float2int_ru(r), SBINS - 1);  // s==0 -> 0 -> bin 0 (= ref)
}

__global__ __launch_bounds__(TPB, CPS)
void ecc_kernel(const float* __restrict__ x, float* __restrict__ out, int n) {
    // u16 hist [56][256]: column tid -> byte 2*tid + 512*bin.
    // bank = tid/2 for ANY bin pattern -> conflict-free RMW.
    __shared__ unsigned short sh[SBINS * TPB];
    __shared__ int      s_u;
    __shared__ float    s_wsum;
    __shared__ unsigned s_last;

    const int tid = threadIdx.x;
    unsigned* h32 = (unsigned*)sh;
    #pragma unroll
    for (int k = tid; k < SBINS * TPB / 2; k += TPB) h32[k] = 0u;

    unsigned short* myh = sh + tid;

    // Dynamic queue over units (2k, 2k+1); expensive (low k) taken first -> LPT
    for (;;) {
        if (tid == 0) s_u = (int)atomicAdd(&g_unit, 1u);
        __syncthreads();                     // also covers zero-init (1st iter)
        const int k = s_u;
        if (k >= NUNITS) break;

        const int i0 = 2 * k;
        const int i1 = 2 * k + 1;
        const float p0x = __ldg(&x[3 * i0 + 0]);
        const float p0y = __ldg(&x[3 * i0 + 1]);
        const float p0z = __ldg(&x[3 * i0 + 2]);
        const float p1x = __ldg(&x[3 * i1 + 0]);
        const float p1y = __ldg(&x[3 * i1 + 1]);
        const float p1z = __ldg(&x[3 * i1 + 2]);

        if (tid == 0) {   // corner pair (i0, i1)
            const int b = pair_bin(p0x - p1x, p0y - p1y, p0z - p1z);
            myh[b * TPB] += 1;
        }

        // Shared j-range: one load -> TWO pairs
        #pragma unroll 4
        for (int j = i0 + 2 + tid; j < n; j += TPB) {
            const float qx = __ldg(&x[3 * j + 0]);
            const float qy = __ldg(&x[3 * j + 1]);
            const float qz = __ldg(&x[3 * j + 2]);
            const int b0 = pair_bin(p0x - qx, p0y - qy, p0z - qz);
            const int b1 = pair_bin(p1x - qx, p1y - qy, p1z - qz);
            myh[b0 * TPB] += 1;
            myh[b1 * TPB] += 1;
        }
        __syncthreads();                     // protect s_u for next fetch
    }
    __syncthreads();                         // RMWs visible to reducers

    // Block-reduce [56][128 words] -> g_hist: 4 threads/bin, rotated banks
    if (tid < SBINS * 4) {
        const int b = tid >> 2;
        const int q = tid & 3;
        const unsigned* hb = h32 + b * 128;
        unsigned sum = 0;
        #pragma unroll
        for (int kk = 0; kk < 32; kk++) {
            const unsigned v = hb[q * 32 + ((kk + tid) & 31)];
            sum += (v & 0xFFFFu) + (v >> 16);
        }
        sum += __shfl_xor_sync(0xffffffffu, sum, 1);
        sum += __shfl_xor_sync(0xffffffffu, sum, 2);
        if (q == 0 && sum) atomicAdd(&g_hist[b], (int)sum);
    }
    __syncthreads();

    // Last-done block: parallel 64-bin read + 2-warp shfl scan
    if (tid == 0) {
        __threadfence();
        s_last = (atomicAdd(&g_done, 1u) == (unsigned)GRID - 1u);
    }
    __syncthreads();
    if (s_last) {
        float v = 0.0f;
        if (tid < NBINS) {
            const int h = atomicAdd(&g_hist[tid], 0);   // 64 parallel reads
            v = -(float)h;
            if (tid == 0) v += (float)n;                // +n vertices at filt 0
            #pragma unroll
            for (int d = 1; d < 32; d <<= 1) {          // inclusive warp scan
                const float t = __shfl_up_sync(0xffffffffu, v, d);
                if ((tid & 31) >= d) v += t;
            }
            if (tid == 31) s_wsum = v;                  // warp0 total
        }
        __syncthreads();
        if (tid < NBINS) {
            if (tid >= 32) v += s_wsum;
            out[tid] = v;
            g_hist[tid] = 0;                            // reset for next replay
        }
        if (tid == 0) { g_unit = 0; g_done = 0; }
    }
}

extern "C" void kernel_launch(void* const* d_in, const int* in_sizes, int n_in,
                              void* d_out, int out_size) {
    const float* x = (const float*)d_in[0];
    float* out = (float*)d_out;
    const int n = in_sizes[0] / 3;   // 4096
    ecc_kernel<<<GRID, TPB>>>(x, out, n);
}

// round 10
// speedup vs baseline: 1.3769x; 1.1212x over previous
#include <cuda_runtime.h>

#define TPB     256
#define NBINS   64
#define SBINS   56           // max bin = ceil(31.5*sqrt(3)) = 55
#define CPS     6            // CTAs per SM (42-reg cap, 48 warps/SM)
#define GRID    (148 * CPS)  // 888 blocks, single wave
#define NUNITS  1024         // units: row quads (4k .. 4k+3)

// Scratch (allocation-free __device__ globals). Zero at entry of every
// launch; the finalizing block resets them (graph-replay safe).
__device__ int      g_hist[NBINS];
__device__ unsigned g_done = 0;
__device__ unsigned g_unit = 0;

__device__ __forceinline__ int pair_bin(float dx, float dy, float dz) {
    const float s = dx * dx + dy * dy + dz * dz;   // FMA ok (tol 1e-3)
    float r;
    // ceil(31.5*sqrt(s)) == ceil(sqrt(992.25*s)); approx err ~1e-7 rel
    asm("sqrt.approx.f32 %0, %1;" : "=f"(r) : "f"(992.25f * s));
    return min(__float2int_ru(r), SBINS - 1);  // s==0 -> 0 -> bin 0 (= ref)
}

__global__ __launch_bounds__(TPB, CPS)
void ecc_kernel(const float* __restrict__ x, float* __restrict__ out, int n) {
    // u16 hist [56][256]: column tid -> byte 2*tid + 512*bin.
    // bank = tid/2 for ANY bin pattern -> conflict-free RMW.
    __shared__ unsigned short sh[SBINS * TPB];
    __shared__ int      s_u;
    __shared__ float    s_wsum;
    __shared__ unsigned s_last;

    const int tid = threadIdx.x;
    unsigned* h32 = (unsigned*)sh;
    #pragma unroll
    for (int k = tid; k < SBINS * TPB / 2; k += TPB) h32[k] = 0u;

    unsigned short* myh = sh + tid;

    // Dynamic queue over row-quads; low k = longest unit, fetched first (LPT)
    for (;;) {
        if (tid == 0) s_u = (int)atomicAdd(&g_unit, 1u);
        __syncthreads();                     // also covers zero-init (1st iter)
        const int k = s_u;
        if (k >= NUNITS) break;

        const int i0 = 4 * k;
        const float p0x = __ldg(&x[3 * i0 + 0]);
        const float p0y = __ldg(&x[3 * i0 + 1]);
        const float p0z = __ldg(&x[3 * i0 + 2]);
        const float p1x = __ldg(&x[3 * i0 + 3]);
        const float p1y = __ldg(&x[3 * i0 + 4]);
        const float p1z = __ldg(&x[3 * i0 + 5]);
        const float p2x = __ldg(&x[3 * i0 + 6]);
        const float p2y = __ldg(&x[3 * i0 + 7]);
        const float p2z = __ldg(&x[3 * i0 + 8]);
        const float p3x = __ldg(&x[3 * i0 + 9]);
        const float p3y = __ldg(&x[3 * i0 + 10]);
        const float p3z = __ldg(&x[3 * i0 + 11]);

        // 6 intra-quad corner pairs: threads 0..5
        if (tid < 6) {
            // (a,b) in {(0,1),(0,2),(0,3),(1,2),(1,3),(2,3)}
            const int a = tid < 3 ? 0 : (tid < 5 ? 1 : 2);
            const int c = tid < 3 ? tid + 1 : (tid < 5 ? tid - 2 : 3);
            const float ax = __ldg(&x[3 * (i0 + a) + 0]);
            const float ay = __ldg(&x[3 * (i0 + a) + 1]);
            const float az = __ldg(&x[3 * (i0 + a) + 2]);
            const float cx = __ldg(&x[3 * (i0 + c) + 0]);
            const float cy = __ldg(&x[3 * (i0 + c) + 1]);
            const float cz = __ldg(&x[3 * (i0 + c) + 2]);
            const int b = pair_bin(ax - cx, ay - cy, az - cz);
            myh[b * TPB] += 1;
        }

        // Shared j-range: one load -> FOUR pairs
        #pragma unroll 2
        for (int j = i0 + 4 + tid; j < n; j += TPB) {
            const float qx = __ldg(&x[3 * j + 0]);
            const float qy = __ldg(&x[3 * j + 1]);
            const float qz = __ldg(&x[3 * j + 2]);
            const int b0 = pair_bin(p0x - qx, p0y - qy, p0z - qz);
            const int b1 = pair_bin(p1x - qx, p1y - qy, p1z - qz);
            const int b2 = pair_bin(p2x - qx, p2y - qy, p2z - qz);
            const int b3 = pair_bin(p3x - qx, p3y - qy, p3z - qz);
            myh[b0 * TPB] += 1;
            myh[b1 * TPB] += 1;
            myh[b2 * TPB] += 1;
            myh[b3 * TPB] += 1;
        }
        __syncthreads();                     // protect s_u for next fetch
    }
    __syncthreads();                         // RMWs visible to reducers

    // Block-reduce [56][128 words] -> g_hist: 4 threads/bin, rotated banks
    if (tid < SBINS * 4) {
        const int b = tid >> 2;
        const int q = tid & 3;
        const unsigned* hb = h32 + b * 128;
        unsigned sum = 0;
        #pragma unroll
        for (int kk = 0; kk < 32; kk++) {
            const unsigned v = hb[q * 32 + ((kk + tid) & 31)];
            sum += (v & 0xFFFFu) + (v >> 16);
        }
        sum += __shfl_xor_sync(0xffffffffu, sum, 1);
        sum += __shfl_xor_sync(0xffffffffu, sum, 2);
        if (q == 0 && sum) atomicAdd(&g_hist[b], (int)sum);
    }
    __syncthreads();

    // Last-done block: parallel 64-bin read + 2-warp shfl scan
    if (tid == 0) {
        __threadfence();
        s_last = (atomicAdd(&g_done, 1u) == (unsigned)GRID - 1u);
    }
    __syncthreads();
    if (s_last) {
        float v = 0.0f;
        if (tid < NBINS) {
            const int h = atomicAdd(&g_hist[tid], 0);   // 64 parallel reads
            v = -(float)h;
            if (tid == 0) v += (float)n;                // +n vertices at filt 0
            #pragma unroll
            for (int d = 1; d < 32; d <<= 1) {          // inclusive warp scan
                const float t = __shfl_up_sync(0xffffffffu, v, d);
                if ((tid & 31) >= d) v += t;
            }
            if (tid == 31) s_wsum = v;                  // warp0 total
        }
        __syncthreads();
        if (tid < NBINS) {
            if (tid >= 32) v += s_wsum;
            out[tid] = v;
            g_hist[tid] = 0;                            // reset for next replay
        }
        if (tid == 0) { g_unit = 0; g_done = 0; }
    }
}

extern "C" void kernel_launch(void* const* d_in, const int* in_sizes, int n_in,
                              void* d_out, int out_size) {
    const float* x = (const float*)d_in[0];
    float* out = (float*)d_out;
    const int n = in_sizes[0] / 3;   // 4096
    ecc_kernel<<<GRID, TPB>>>(x, out, n);
}